// round 2
// baseline (speedup 1.0000x reference)
#include <cuda_runtime.h>
#include <cstdint>

// Propagate: 3-hop fixed-degree(16) CSR SpMM, N=100000 nodes, D=64 f32 features.
// out = A^3 x. NOTE: JAX default x64-disabled means indptr/indices arrive as
// int32 despite the reference's jnp.int64 annotation.
//
// Strategy: one warp per output row. Each lane owns a float2 (32 lanes x 2 floats
// = 64 features). Lanes 0..15 preload the row's 16 (index,value) pairs; the loop
// broadcasts them with __shfl_sync. The 16 gathered rows are 256B coalesced loads,
// independent across the unrolled loop (MLP=16). The 25.6MB feature matrix fits
// in L2, so gathers are mostly L2-resident.

#define N_NODES 100000
#define DEG 16
#define D_FEAT 64
#define D_VEC2 (D_FEAT / 2)   // 32 float2 per row

// Ping-pong scratch (allocation-free): 100000 * 64 floats = 25.6 MB each.
__device__ float g_buf0[(size_t)N_NODES * D_FEAT];
__device__ float g_buf1[(size_t)N_NODES * D_FEAT];

__global__ void __launch_bounds__(256) hop_kernel(
    const float2* __restrict__ xin,
    const float*  __restrict__ values,
    const int*    __restrict__ indices,
    float2* __restrict__ xout,
    int n_nodes)
{
    int gwarp = (blockIdx.x * blockDim.x + threadIdx.x) >> 5;
    int lane  = threadIdx.x & 31;
    if (gwarp >= n_nodes) return;

    int ebase = gwarp * DEG;

    // Lanes 0..15 hold this row's edges.
    int   nb_idx = 0;
    float ev     = 0.0f;
    if (lane < DEG) {
        nb_idx = indices[ebase + lane];
        ev     = values[ebase + lane];
    }

    float2 acc = make_float2(0.0f, 0.0f);

#pragma unroll
    for (int e = 0; e < DEG; ++e) {
        int   nb = __shfl_sync(0xFFFFFFFFu, nb_idx, e);
        float w  = __shfl_sync(0xFFFFFFFFu, ev,     e);
        float2 xv = xin[(long long)nb * D_VEC2 + lane];
        acc.x = fmaf(w, xv.x, acc.x);
        acc.y = fmaf(w, xv.y, acc.y);
    }

    xout[(long long)gwarp * D_VEC2 + lane] = acc;
}

extern "C" void kernel_launch(void* const* d_in, const int* in_sizes, int n_in,
                              void* d_out, int out_size)
{
    const float* x       = (const float*)d_in[0];   // [N, 64] f32
    const float* values  = (const float*)d_in[1];   // [E] f32
    // d_in[2] = indptr (int32) — fixed stride DEG, unused
    const int*   indices = (const int*)d_in[3];     // [E] int32
    float* out = (float*)d_out;

    int n_nodes = in_sizes[0] / D_FEAT;

    float* buf0;
    float* buf1;
    cudaGetSymbolAddress((void**)&buf0, g_buf0);
    cudaGetSymbolAddress((void**)&buf1, g_buf1);

    int threads = 256;
    int warps_per_block = threads / 32;
    int blocks = (n_nodes + warps_per_block - 1) / warps_per_block;

    // hop 1: x -> buf0
    hop_kernel<<<blocks, threads>>>((const float2*)x, values, indices,
                                    (float2*)buf0, n_nodes);
    // hop 2: buf0 -> buf1
    hop_kernel<<<blocks, threads>>>((const float2*)buf0, values, indices,
                                    (float2*)buf1, n_nodes);
    // hop 3: buf1 -> out
    hop_kernel<<<blocks, threads>>>((const float2*)buf1, values, indices,
                                    (float2*)out, n_nodes);
}

// round 3
// speedup vs baseline: 1.1900x; 1.1900x over previous
#include <cuda_runtime.h>
#include <cstdint>

// Propagate: 3-hop fixed-degree(16) CSR SpMM, N=100000 nodes, D=64 f32 features.
// out = A^3 x. indices/values arrive int32/f32 (JAX x64-disabled).
//
// R3 layout: 2 rows per warp. Each lane owns a float4; lanes 0..15 cover row
// r0=2w, lanes 16..31 cover row r1=2w+1 (16 lanes x 16B = 256B = one row).
// A single warp-wide LDG.128 gathers BOTH rows' neighbor e in one instruction
// (one LSU queue entry for 512B), halving gather-instruction count vs R2.
// Edge (idx,val) loads are coalesced: lane l holds edge l of the row pair;
// shuffle srcLane=(lane&16)|e broadcasts edge e to the matching half-warp.

#define N_NODES 100000
#define DEG 16
#define D_FEAT 64
#define D_VEC4 (D_FEAT / 4)   // 16 float4 per row

__device__ float g_buf0[(size_t)N_NODES * D_FEAT];
__device__ float g_buf1[(size_t)N_NODES * D_FEAT];

__global__ void __launch_bounds__(256) hop_kernel(
    const float4* __restrict__ xin,
    const float*  __restrict__ values,
    const int*    __restrict__ indices,
    float4* __restrict__ xout,
    int n_nodes)
{
    int gwarp = (blockIdx.x * blockDim.x + threadIdx.x) >> 5;
    int lane  = threadIdx.x & 31;

    int r0 = gwarp * 2;
    if (r0 >= n_nodes) return;

    int lane16 = lane & 15;
    int src_hi = lane & 16;            // 0 for row r0 lanes, 16 for row r1 lanes

    // Lane l holds edge l of the row pair (rows r0,r1 own edges [r0*16, r0*16+32)).
    int eidx = r0 * DEG + lane;
    int emax = n_nodes * DEG - 1;
    if (eidx > emax) eidx = emax;      // clamp (only matters for odd tail)
    int   nb_idx = indices[eidx];
    float ev     = values[eidx];

    float4 acc = make_float4(0.0f, 0.0f, 0.0f, 0.0f);

#pragma unroll
    for (int e = 0; e < DEG; ++e) {
        int   nb = __shfl_sync(0xFFFFFFFFu, nb_idx, src_hi | e);
        float w  = __shfl_sync(0xFFFFFFFFu, ev,     src_hi | e);
        float4 xv = xin[(long long)nb * D_VEC4 + lane16];
        acc.x = fmaf(w, xv.x, acc.x);
        acc.y = fmaf(w, xv.y, acc.y);
        acc.z = fmaf(w, xv.z, acc.z);
        acc.w = fmaf(w, xv.w, acc.w);
    }

    int r = r0 + (lane >> 4);
    if (r < n_nodes)
        xout[(long long)r * D_VEC4 + lane16] = acc;
}

extern "C" void kernel_launch(void* const* d_in, const int* in_sizes, int n_in,
                              void* d_out, int out_size)
{
    const float* x       = (const float*)d_in[0];   // [N, 64] f32
    const float* values  = (const float*)d_in[1];   // [E] f32
    // d_in[2] = indptr — fixed stride DEG, unused
    const int*   indices = (const int*)d_in[3];     // [E] int32
    float* out = (float*)d_out;

    int n_nodes = in_sizes[0] / D_FEAT;

    float* buf0;
    float* buf1;
    cudaGetSymbolAddress((void**)&buf0, g_buf0);
    cudaGetSymbolAddress((void**)&buf1, g_buf1);

    int threads = 256;
    int rows_per_block = (threads / 32) * 2;   // 2 rows per warp
    int blocks = (n_nodes + rows_per_block - 1) / rows_per_block;

    hop_kernel<<<blocks, threads>>>((const float4*)x, values, indices,
                                    (float4*)buf0, n_nodes);
    hop_kernel<<<blocks, threads>>>((const float4*)buf0, values, indices,
                                    (float4*)buf1, n_nodes);
    hop_kernel<<<blocks, threads>>>((const float4*)buf1, values, indices,
                                    (float4*)out, n_nodes);
}